// round 1
// baseline (speedup 1.0000x reference)
#include <cuda_runtime.h>
#include <math.h>

#define BB 2
#define SS 2048
#define HQN 32
#define HKV 8
#define DD 128
#define SCALING 0.08838834764831845f

#define BM 64
#define BN 64
#define PPITCH 68

// Dequantized KV scratch, layout [b][hkv][s][d]
__device__ float g_kd[(size_t)BB * HKV * SS * DD];
__device__ float g_vd[(size_t)BB * HKV * SS * DD];

// ---------------------------------------------------------------------------
// e4m3 quant-dequant, bit-faithful to the JAX reference:
//   e = clip(floor(log2(|x|)), -6, 8); q = round(clip(x,±448)*2^(3-e))*2^(e-3)
// ilogbf == floor(log2(|x|)) exactly; rintf == round-half-even; ldexpf exact.
// ---------------------------------------------------------------------------
__device__ __forceinline__ float e4m3_qd(float x) {
    float ax = fabsf(x);
    if (ax == 0.0f) return 0.0f;
    float xc = fminf(fmaxf(x, -448.0f), 448.0f);
    int e = ilogbf(ax);
    e = e < -6 ? -6 : (e > 8 ? 8 : e);
    return ldexpf(rintf(ldexpf(xc, 3 - e)), e - 3);
}

// One warp per (b, s, hkv) row of 128: e4m3 per element, warp absmax,
// FP4 (e2m1) with scale = absmax/6 (IEEE div, matching jnp), searchsorted-left
// midpoints, (sign*grid)*scale association matching the reference.
__global__ void prep_kernel(const float* __restrict__ src, int which) {
    float* __restrict__ dst = which ? g_vd : g_kd;
    int gw = (blockIdx.x * blockDim.x + threadIdx.x) >> 5;
    if (gw >= BB * SS * HKV) return;
    int lane = threadIdx.x & 31;
    int h = gw % HKV;
    int t = gw / HKV;
    int s = t % SS;
    int b = t / SS;

    const float4* p = (const float4*)(src + ((size_t)(b * SS + s) * HKV + h) * DD);
    float4 xv = p[lane];
    float qq[4];
    qq[0] = e4m3_qd(xv.x);
    qq[1] = e4m3_qd(xv.y);
    qq[2] = e4m3_qd(xv.z);
    qq[3] = e4m3_qd(xv.w);

    float am = fmaxf(fmaxf(fabsf(qq[0]), fabsf(qq[1])), fmaxf(fabsf(qq[2]), fabsf(qq[3])));
    #pragma unroll
    for (int o = 16; o >= 1; o >>= 1)
        am = fmaxf(am, __shfl_xor_sync(0xffffffffu, am, o));

    float scale = fmaxf(__fdiv_rn(am, 6.0f), 1e-12f);

    float r[4];
    #pragma unroll
    for (int u = 0; u < 4; ++u) {
        float xn = __fdiv_rn(qq[u], scale);
        float axn = fabsf(xn);
        float g = axn <= 0.25f ? 0.0f :
                  axn <= 0.75f ? 0.5f :
                  axn <= 1.25f ? 1.0f :
                  axn <= 1.75f ? 1.5f :
                  axn <= 2.5f  ? 2.0f :
                  axn <= 3.5f  ? 3.0f :
                  axn <= 5.0f  ? 4.0f : 6.0f;
        float sg = xn > 0.0f ? 1.0f : (xn < 0.0f ? -1.0f : 0.0f);
        r[u] = (sg * g) * scale;
    }

    float4* op = (float4*)(dst + ((size_t)(b * HKV + h) * SS + s) * DD);
    op[lane] = make_float4(r[0], r[1], r[2], r[3]);
}

// ---------------------------------------------------------------------------
// fp32 flash attention. One CTA per (q-tile, b*hq). 256 threads.
// GEMM1: S = Qs(64x128) * Ks(64x128)^T, 4x4 reg tile, K smem XOR-swizzled.
// Online softmax across tx (16-lane row groups).
// GEMM2: O += P(64x64) * Vs(64x128), 4x8 reg tile.
// ---------------------------------------------------------------------------
__global__ __launch_bounds__(256, 1)
void attn_kernel(const float* __restrict__ q, float* __restrict__ out) {
    extern __shared__ float sm[];
    float4* Qs = (float4*)sm;                    // [64][32] float4
    float4* Ks = (float4*)(sm + 64 * 128);       // [64][32] float4, swizzled
    float4* Vs = (float4*)(sm + 2 * 64 * 128);   // [64][32] float4
    float*  Ps = sm + 3 * 64 * 128;              // [64][PPITCH]

    int tid = threadIdx.x;
    int tx = tid & 15, ty = tid >> 4;
    int idx = blockIdx.x;
    int bh = idx & 63;
    int mt = idx >> 6;
    int b = bh >> 5, hq = bh & 31;
    int hkv = hq >> 2;
    int m0 = mt * BM;

    // Load Q tile, pre-scaled by SCALING (fp32 rounding diff vs post-scale is ~2^-24)
    {
        int c = tid & 31, rr = tid >> 5;
        const float* qb = q + ((size_t)(b * SS + m0) * HQN + hq) * DD;
        #pragma unroll
        for (int j = 0; j < 8; ++j) {
            int m = j * 8 + rr;
            float4 v = *(const float4*)(qb + (size_t)m * HQN * DD + c * 4);
            v.x *= SCALING; v.y *= SCALING; v.z *= SCALING; v.w *= SCALING;
            Qs[m * 32 + c] = v;
        }
    }

    float acc[4][8];
    #pragma unroll
    for (int i = 0; i < 4; ++i)
        #pragma unroll
        for (int j = 0; j < 8; ++j) acc[i][j] = 0.0f;
    float mrow[4] = {-1e30f, -1e30f, -1e30f, -1e30f};
    float lrow[4] = {0.0f, 0.0f, 0.0f, 0.0f};

    const float* kb = g_kd + (size_t)(b * HKV + hkv) * SS * DD;
    const float* vb = g_vd + (size_t)(b * HKV + hkv) * SS * DD;

    int ntiles = mt + 1;
    for (int t = 0; t < ntiles; ++t) {
        int n0 = t * BN;
        __syncthreads();  // protect Ks/Vs/Ps against previous iteration's readers
        {
            int c = tid & 31, rr = tid >> 5;
            #pragma unroll
            for (int j = 0; j < 8; ++j) {
                int n = j * 8 + rr;
                float4 kv = *(const float4*)(kb + (size_t)(n0 + n) * DD + c * 4);
                Ks[n * 32 + (c ^ ((n >> 2) & 7))] = kv;
                float4 vv = *(const float4*)(vb + (size_t)(n0 + n) * DD + c * 4);
                Vs[n * 32 + c] = vv;
            }
        }
        __syncthreads();

        // GEMM1: s[i][j] = sum_k Q[m][k] * K[n][k]
        float s[4][4];
        #pragma unroll
        for (int i = 0; i < 4; ++i)
            #pragma unroll
            for (int j = 0; j < 4; ++j) s[i][j] = 0.0f;

        int swz = tx & 7;
        #pragma unroll 8
        for (int kk = 0; kk < 32; ++kk) {
            float4 qv[4], kv[4];
            #pragma unroll
            for (int i = 0; i < 4; ++i) qv[i] = Qs[(ty * 4 + i) * 32 + kk];
            #pragma unroll
            for (int j = 0; j < 4; ++j) kv[j] = Ks[(tx * 4 + j) * 32 + (kk ^ swz)];
            #pragma unroll
            for (int i = 0; i < 4; ++i)
                #pragma unroll
                for (int j = 0; j < 4; ++j) {
                    s[i][j] += qv[i].x * kv[j].x;
                    s[i][j] += qv[i].y * kv[j].y;
                    s[i][j] += qv[i].z * kv[j].z;
                    s[i][j] += qv[i].w * kv[j].w;
                }
        }

        // Causal mask only on the diagonal tile
        if (t == ntiles - 1) {
            #pragma unroll
            for (int i = 0; i < 4; ++i)
                #pragma unroll
                for (int j = 0; j < 4; ++j)
                    if (n0 + tx * 4 + j > m0 + ty * 4 + i) s[i][j] = -1e30f;
        }

        // Online softmax: row group = 16 lanes sharing ty
        #pragma unroll
        for (int i = 0; i < 4; ++i) {
            float mx = fmaxf(fmaxf(s[i][0], s[i][1]), fmaxf(s[i][2], s[i][3]));
            #pragma unroll
            for (int o = 8; o >= 1; o >>= 1)
                mx = fmaxf(mx, __shfl_xor_sync(0xffffffffu, mx, o));
            float mnew = fmaxf(mrow[i], mx);
            float corr = __expf(mrow[i] - mnew);
            float p0 = __expf(s[i][0] - mnew);
            float p1 = __expf(s[i][1] - mnew);
            float p2 = __expf(s[i][2] - mnew);
            float p3 = __expf(s[i][3] - mnew);
            float rs = p0 + p1 + p2 + p3;
            #pragma unroll
            for (int o = 8; o >= 1; o >>= 1)
                rs += __shfl_xor_sync(0xffffffffu, rs, o);
            lrow[i] = lrow[i] * corr + rs;
            mrow[i] = mnew;
            #pragma unroll
            for (int j = 0; j < 8; ++j) acc[i][j] *= corr;
            *(float4*)(Ps + (ty * 4 + i) * PPITCH + tx * 4) = make_float4(p0, p1, p2, p3);
        }
        __syncthreads();

        // GEMM2: acc[i][*] += P[m][n] * V[n][d], d = tx*8 .. tx*8+7
        #pragma unroll 4
        for (int n = 0; n < BN; ++n) {
            float pv[4];
            #pragma unroll
            for (int i = 0; i < 4; ++i) pv[i] = Ps[(ty * 4 + i) * PPITCH + n];
            float4 v0 = Vs[n * 32 + tx * 2];
            float4 v1 = Vs[n * 32 + tx * 2 + 1];
            #pragma unroll
            for (int i = 0; i < 4; ++i) {
                acc[i][0] += pv[i] * v0.x;
                acc[i][1] += pv[i] * v0.y;
                acc[i][2] += pv[i] * v0.z;
                acc[i][3] += pv[i] * v0.w;
                acc[i][4] += pv[i] * v1.x;
                acc[i][5] += pv[i] * v1.y;
                acc[i][6] += pv[i] * v1.z;
                acc[i][7] += pv[i] * v1.w;
            }
        }
    }

    // Epilogue: normalize and store
    #pragma unroll
    for (int i = 0; i < 4; ++i) {
        float inv = 1.0f / lrow[i];
        int m = m0 + ty * 4 + i;
        float* op = out + ((size_t)(b * SS + m) * HQN + hq) * DD + tx * 8;
        *(float4*)op = make_float4(acc[i][0] * inv, acc[i][1] * inv,
                                   acc[i][2] * inv, acc[i][3] * inv);
        *(float4*)(op + 4) = make_float4(acc[i][4] * inv, acc[i][5] * inv,
                                         acc[i][6] * inv, acc[i][7] * inv);
    }
}

extern "C" void kernel_launch(void* const* d_in, const int* in_sizes, int n_in,
                              void* d_out, int out_size) {
    (void)in_sizes; (void)n_in; (void)out_size;
    const float* q = (const float*)d_in[0];
    const float* k = (const float*)d_in[1];
    const float* v = (const float*)d_in[2];
    float* out = (float*)d_out;

    const int smem_bytes = (3 * 64 * 128 + 64 * PPITCH) * 4;  // 115712
    cudaFuncSetAttribute(attn_kernel, cudaFuncAttributeMaxDynamicSharedMemorySize,
                         smem_bytes);

    int prep_rows = BB * SS * HKV;                  // 32768 warps
    int prep_blocks = (prep_rows * 32 + 255) / 256; // 4096
    prep_kernel<<<prep_blocks, 256>>>(k, 0);
    prep_kernel<<<prep_blocks, 256>>>(v, 1);

    attn_kernel<<<(SS / BM) * BB * HQN, 256, smem_bytes>>>(q, out);
}

// round 2
// speedup vs baseline: 1.0003x; 1.0003x over previous
#include <cuda_runtime.h>
#include <math.h>

#define BB 2
#define SS 2048
#define HQN 32
#define HKV 8
#define DD 128
#define SCALING 0.08838834764831845f

#define BM 64
#define BN 64
#define PPITCH 68

// Dequantized KV scratch, layout [b][hkv][s][d]
__device__ float g_kd[(size_t)BB * HKV * SS * DD];
__device__ float g_vd[(size_t)BB * HKV * SS * DD];

// ---------------------------------------------------------------------------
// e4m3 quant-dequant, bit-faithful to the JAX reference:
//   e = clip(floor(log2(|x|)), -6, 8); q = round(clip(x,±448)*2^(3-e))*2^(e-3)
// ilogbf == floor(log2(|x|)) exactly; rintf == round-half-even; ldexpf exact.
// ---------------------------------------------------------------------------
__device__ __forceinline__ float e4m3_qd(float x) {
    float ax = fabsf(x);
    if (ax == 0.0f) return 0.0f;
    float xc = fminf(fmaxf(x, -448.0f), 448.0f);
    int e = ilogbf(ax);
    e = e < -6 ? -6 : (e > 8 ? 8 : e);
    return ldexpf(rintf(ldexpf(xc, 3 - e)), e - 3);
}

// One warp per (b, s, hkv) row of 128: e4m3 per element, warp absmax,
// FP4 (e2m1) with scale = absmax/6 (IEEE div, matching jnp), searchsorted-left
// midpoints, (sign*grid)*scale association matching the reference.
__global__ void prep_kernel(const float* __restrict__ src, int which) {
    float* __restrict__ dst = which ? g_vd : g_kd;
    int gw = (blockIdx.x * blockDim.x + threadIdx.x) >> 5;
    if (gw >= BB * SS * HKV) return;
    int lane = threadIdx.x & 31;
    int h = gw % HKV;
    int t = gw / HKV;
    int s = t % SS;
    int b = t / SS;

    const float4* p = (const float4*)(src + ((size_t)(b * SS + s) * HKV + h) * DD);
    float4 xv = p[lane];
    float qq[4];
    qq[0] = e4m3_qd(xv.x);
    qq[1] = e4m3_qd(xv.y);
    qq[2] = e4m3_qd(xv.z);
    qq[3] = e4m3_qd(xv.w);

    float am = fmaxf(fmaxf(fabsf(qq[0]), fabsf(qq[1])), fmaxf(fabsf(qq[2]), fabsf(qq[3])));
    #pragma unroll
    for (int o = 16; o >= 1; o >>= 1)
        am = fmaxf(am, __shfl_xor_sync(0xffffffffu, am, o));

    float scale = fmaxf(__fdiv_rn(am, 6.0f), 1e-12f);

    float r[4];
    #pragma unroll
    for (int u = 0; u < 4; ++u) {
        float xn = __fdiv_rn(qq[u], scale);
        float axn = fabsf(xn);
        float g = axn <= 0.25f ? 0.0f :
                  axn <= 0.75f ? 0.5f :
                  axn <= 1.25f ? 1.0f :
                  axn <= 1.75f ? 1.5f :
                  axn <= 2.5f  ? 2.0f :
                  axn <= 3.5f  ? 3.0f :
                  axn <= 5.0f  ? 4.0f : 6.0f;
        float sg = xn > 0.0f ? 1.0f : (xn < 0.0f ? -1.0f : 0.0f);
        r[u] = (sg * g) * scale;
    }

    float4* op = (float4*)(dst + ((size_t)(b * HKV + h) * SS + s) * DD);
    op[lane] = make_float4(r[0], r[1], r[2], r[3]);
}

// ---------------------------------------------------------------------------
// fp32 flash attention. One CTA per (q-tile, b*hq). 256 threads.
// GEMM1: S = Qs(64x128) * Ks(64x128)^T, 4x4 reg tile, K smem XOR-swizzled.
// Online softmax across tx (16-lane row groups).
// GEMM2: O += P(64x64) * Vs(64x128), 4x8 reg tile.
// ---------------------------------------------------------------------------
__global__ __launch_bounds__(256, 1)
void attn_kernel(const float* __restrict__ q, float* __restrict__ out) {
    extern __shared__ float sm[];
    float4* Qs = (float4*)sm;                    // [64][32] float4
    float4* Ks = (float4*)(sm + 64 * 128);       // [64][32] float4, swizzled
    float4* Vs = (float4*)(sm + 2 * 64 * 128);   // [64][32] float4
    float*  Ps = sm + 3 * 64 * 128;              // [64][PPITCH]

    int tid = threadIdx.x;
    int tx = tid & 15, ty = tid >> 4;
    int idx = blockIdx.x;
    int bh = idx & 63;
    int mt = idx >> 6;
    int b = bh >> 5, hq = bh & 31;
    int hkv = hq >> 2;
    int m0 = mt * BM;

    // Load Q tile, pre-scaled by SCALING (fp32 rounding diff vs post-scale is ~2^-24)
    {
        int c = tid & 31, rr = tid >> 5;
        const float* qb = q + ((size_t)(b * SS + m0) * HQN + hq) * DD;
        #pragma unroll
        for (int j = 0; j < 8; ++j) {
            int m = j * 8 + rr;
            float4 v = *(const float4*)(qb + (size_t)m * HQN * DD + c * 4);
            v.x *= SCALING; v.y *= SCALING; v.z *= SCALING; v.w *= SCALING;
            Qs[m * 32 + c] = v;
        }
    }

    float acc[4][8];
    #pragma unroll
    for (int i = 0; i < 4; ++i)
        #pragma unroll
        for (int j = 0; j < 8; ++j) acc[i][j] = 0.0f;
    float mrow[4] = {-1e30f, -1e30f, -1e30f, -1e30f};
    float lrow[4] = {0.0f, 0.0f, 0.0f, 0.0f};

    const float* kb = g_kd + (size_t)(b * HKV + hkv) * SS * DD;
    const float* vb = g_vd + (size_t)(b * HKV + hkv) * SS * DD;

    int ntiles = mt + 1;
    for (int t = 0; t < ntiles; ++t) {
        int n0 = t * BN;
        __syncthreads();  // protect Ks/Vs/Ps against previous iteration's readers
        {
            int c = tid & 31, rr = tid >> 5;
            #pragma unroll
            for (int j = 0; j < 8; ++j) {
                int n = j * 8 + rr;
                float4 kv = *(const float4*)(kb + (size_t)(n0 + n) * DD + c * 4);
                Ks[n * 32 + (c ^ ((n >> 2) & 7))] = kv;
                float4 vv = *(const float4*)(vb + (size_t)(n0 + n) * DD + c * 4);
                Vs[n * 32 + c] = vv;
            }
        }
        __syncthreads();

        // GEMM1: s[i][j] = sum_k Q[m][k] * K[n][k]
        float s[4][4];
        #pragma unroll
        for (int i = 0; i < 4; ++i)
            #pragma unroll
            for (int j = 0; j < 4; ++j) s[i][j] = 0.0f;

        int swz = tx & 7;
        #pragma unroll 8
        for (int kk = 0; kk < 32; ++kk) {
            float4 qv[4], kv[4];
            #pragma unroll
            for (int i = 0; i < 4; ++i) qv[i] = Qs[(ty * 4 + i) * 32 + kk];
            #pragma unroll
            for (int j = 0; j < 4; ++j) kv[j] = Ks[(tx * 4 + j) * 32 + (kk ^ swz)];
            #pragma unroll
            for (int i = 0; i < 4; ++i)
                #pragma unroll
                for (int j = 0; j < 4; ++j) {
                    s[i][j] += qv[i].x * kv[j].x;
                    s[i][j] += qv[i].y * kv[j].y;
                    s[i][j] += qv[i].z * kv[j].z;
                    s[i][j] += qv[i].w * kv[j].w;
                }
        }

        // Causal mask only on the diagonal tile
        if (t == ntiles - 1) {
            #pragma unroll
            for (int i = 0; i < 4; ++i)
                #pragma unroll
                for (int j = 0; j < 4; ++j)
                    if (n0 + tx * 4 + j > m0 + ty * 4 + i) s[i][j] = -1e30f;
        }

        // Online softmax: row group = 16 lanes sharing ty
        #pragma unroll
        for (int i = 0; i < 4; ++i) {
            float mx = fmaxf(fmaxf(s[i][0], s[i][1]), fmaxf(s[i][2], s[i][3]));
            #pragma unroll
            for (int o = 8; o >= 1; o >>= 1)
                mx = fmaxf(mx, __shfl_xor_sync(0xffffffffu, mx, o));
            float mnew = fmaxf(mrow[i], mx);
            float corr = __expf(mrow[i] - mnew);
            float p0 = __expf(s[i][0] - mnew);
            float p1 = __expf(s[i][1] - mnew);
            float p2 = __expf(s[i][2] - mnew);
            float p3 = __expf(s[i][3] - mnew);
            float rs = p0 + p1 + p2 + p3;
            #pragma unroll
            for (int o = 8; o >= 1; o >>= 1)
                rs += __shfl_xor_sync(0xffffffffu, rs, o);
            lrow[i] = lrow[i] * corr + rs;
            mrow[i] = mnew;
            #pragma unroll
            for (int j = 0; j < 8; ++j) acc[i][j] *= corr;
            *(float4*)(Ps + (ty * 4 + i) * PPITCH + tx * 4) = make_float4(p0, p1, p2, p3);
        }
        __syncthreads();

        // GEMM2: acc[i][*] += P[m][n] * V[n][d], d = tx*8 .. tx*8+7
        #pragma unroll 4
        for (int n = 0; n < BN; ++n) {
            float pv[4];
            #pragma unroll
            for (int i = 0; i < 4; ++i) pv[i] = Ps[(ty * 4 + i) * PPITCH + n];
            float4 v0 = Vs[n * 32 + tx * 2];
            float4 v1 = Vs[n * 32 + tx * 2 + 1];
            #pragma unroll
            for (int i = 0; i < 4; ++i) {
                acc[i][0] += pv[i] * v0.x;
                acc[i][1] += pv[i] * v0.y;
                acc[i][2] += pv[i] * v0.z;
                acc[i][3] += pv[i] * v0.w;
                acc[i][4] += pv[i] * v1.x;
                acc[i][5] += pv[i] * v1.y;
                acc[i][6] += pv[i] * v1.z;
                acc[i][7] += pv[i] * v1.w;
            }
        }
    }

    // Epilogue: normalize and store
    #pragma unroll
    for (int i = 0; i < 4; ++i) {
        float inv = 1.0f / lrow[i];
        int m = m0 + ty * 4 + i;
        float* op = out + ((size_t)(b * SS + m) * HQN + hq) * DD + tx * 8;
        *(float4*)op = make_float4(acc[i][0] * inv, acc[i][1] * inv,
                                   acc[i][2] * inv, acc[i][3] * inv);
        *(float4*)(op + 4) = make_float4(acc[i][4] * inv, acc[i][5] * inv,
                                         acc[i][6] * inv, acc[i][7] * inv);
    }
}

extern "C" void kernel_launch(void* const* d_in, const int* in_sizes, int n_in,
                              void* d_out, int out_size) {
    (void)in_sizes; (void)n_in; (void)out_size;
    const float* q = (const float*)d_in[0];
    const float* k = (const float*)d_in[1];
    const float* v = (const float*)d_in[2];
    float* out = (float*)d_out;

    const int smem_bytes = (3 * 64 * 128 + 64 * PPITCH) * 4;  // 115712
    cudaFuncSetAttribute(attn_kernel, cudaFuncAttributeMaxDynamicSharedMemorySize,
                         smem_bytes);

    int prep_rows = BB * SS * HKV;                  // 32768 warps
    int prep_blocks = (prep_rows * 32 + 255) / 256; // 4096
    prep_kernel<<<prep_blocks, 256>>>(k, 0);
    prep_kernel<<<prep_blocks, 256>>>(v, 1);

    attn_kernel<<<(SS / BM) * BB * HQN, 256, smem_bytes>>>(q, out);
}

// round 5
// speedup vs baseline: 5.4038x; 5.4020x over previous
#include <cuda_runtime.h>
#include <cuda_bf16.h>
#include <math.h>
#include <stdint.h>

#define BB 2
#define SS 2048
#define HQN 32
#define HKV 8
#define DD 128
#define SCALING 0.08838834764831845f

// ---------------- device scratch ----------------
__device__ __nv_bfloat16 g_kg[(size_t)BB * HKV * SS * DD];  // K fp4-grid bf16 [b][h][s][d]
__device__ __nv_bfloat16 g_vg[(size_t)BB * HKV * SS * DD];  // V fp4-grid bf16 [b][h][s][d]
__device__ float g_sk[(size_t)BB * HKV * SS];
__device__ float g_sv[(size_t)BB * HKV * SS];

// ---------------- prep: e4m3 qd -> fp4 grid + per-row scale ----------------
__device__ __forceinline__ float e4m3_qd(float x) {
    float ax = fabsf(x);
    if (ax == 0.0f) return 0.0f;
    float xc = fminf(fmaxf(x, -448.0f), 448.0f);
    int e = ilogbf(ax);
    e = e < -6 ? -6 : (e > 8 ? 8 : e);
    return ldexpf(rintf(ldexpf(xc, 3 - e)), e - 3);
}

__global__ void prep_kernel(const float* __restrict__ src, int which) {
    int gw = (blockIdx.x * blockDim.x + threadIdx.x) >> 5;
    if (gw >= BB * SS * HKV) return;
    int lane = threadIdx.x & 31;
    int h = gw % HKV;
    int t = gw / HKV;
    int s = t % SS;
    int b = t / SS;

    const float4* p = (const float4*)(src + ((size_t)(b * SS + s) * HKV + h) * DD);
    float4 xv = p[lane];
    float qq[4];
    qq[0] = e4m3_qd(xv.x); qq[1] = e4m3_qd(xv.y);
    qq[2] = e4m3_qd(xv.z); qq[3] = e4m3_qd(xv.w);

    float am = fmaxf(fmaxf(fabsf(qq[0]), fabsf(qq[1])), fmaxf(fabsf(qq[2]), fabsf(qq[3])));
    #pragma unroll
    for (int o = 16; o >= 1; o >>= 1)
        am = fmaxf(am, __shfl_xor_sync(0xffffffffu, am, o));
    float scale = fmaxf(__fdiv_rn(am, 6.0f), 1e-12f);

    float r[4];
    #pragma unroll
    for (int u = 0; u < 4; ++u) {
        float xn = __fdiv_rn(qq[u], scale);
        float axn = fabsf(xn);
        float g = axn <= 0.25f ? 0.0f :
                  axn <= 0.75f ? 0.5f :
                  axn <= 1.25f ? 1.0f :
                  axn <= 1.75f ? 1.5f :
                  axn <= 2.5f  ? 2.0f :
                  axn <= 3.5f  ? 3.0f :
                  axn <= 5.0f  ? 4.0f : 6.0f;
        float sg = xn > 0.0f ? 1.0f : (xn < 0.0f ? -1.0f : 0.0f);
        r[u] = sg * g;  // exact in bf16
    }

    size_t bh = (size_t)(b * HKV + h);
    __nv_bfloat16* dst = (which ? g_vg : g_kg) + (bh * SS + s) * DD + lane * 4;
    dst[0] = __float2bfloat16_rn(r[0]); dst[1] = __float2bfloat16_rn(r[1]);
    dst[2] = __float2bfloat16_rn(r[2]); dst[3] = __float2bfloat16_rn(r[3]);
    if (lane == 0) (which ? g_sv : g_sk)[bh * SS + s] = scale;
}

// ---------------- mma.sync helpers ----------------
__device__ __forceinline__ uint32_t smem_u32(const void* p) {
    uint32_t a;
    asm("{ .reg .u64 t; cvta.to.shared.u64 t, %1; cvt.u32.u64 %0, t; }" : "=r"(a) : "l"(p));
    return a;
}

#define MMA_BF16(c, a0, a1, a2, a3, b0, b1)                                     \
    asm volatile("mma.sync.aligned.m16n8k16.row.col.f32.bf16.bf16.f32 "         \
        "{%0,%1,%2,%3}, {%4,%5,%6,%7}, {%8,%9}, {%0,%1,%2,%3};"                 \
        : "+f"((c)[0]), "+f"((c)[1]), "+f"((c)[2]), "+f"((c)[3])                \
        : "r"(a0), "r"(a1), "r"(a2), "r"(a3), "r"(b0), "r"(b1))

#define LDSM4(r, a)                                                             \
    asm volatile("ldmatrix.sync.aligned.m8n8.x4.shared.b16 {%0,%1,%2,%3}, [%4];" \
        : "=r"((r)[0]), "=r"((r)[1]), "=r"((r)[2]), "=r"((r)[3]) : "r"(a))

#define LDSM4T(r, a)                                                            \
    asm volatile("ldmatrix.sync.aligned.m8n8.x4.trans.shared.b16 {%0,%1,%2,%3}, [%4];" \
        : "=r"((r)[0]), "=r"((r)[1]), "=r"((r)[2]), "=r"((r)[3]) : "r"(a))

__device__ __forceinline__ uint32_t pack_bf16(__nv_bfloat16 lo, __nv_bfloat16 hi) {
    return ((uint32_t)__bfloat16_as_ushort(hi) << 16) | __bfloat16_as_ushort(lo);
}

// smem pitch: 136 bf16 (272 B) per 128-element row -> pad 8; ldmatrix row phase
// hits banks (r*68)%32 = 4r mod 32, all distinct -> conflict-free.
#define PITCH 136
#define OFF_QH 0
#define OFF_QL (64 * PITCH)
#define OFF_K  (2 * 64 * PITCH)
#define OFF_V  (3 * 64 * PITCH)
#define SK_OFF (4 * 64 * PITCH)         // floats stored via cast
#define SMEM_HALFS (4 * 64 * PITCH + 256)
#define SMEM_BYTES (SMEM_HALFS * 2)

// ---------------- flash attention via mma.sync ----------------
__global__ __launch_bounds__(128)
void attn_kernel(const float* __restrict__ q, float* __restrict__ out) {
    extern __shared__ __align__(16) __nv_bfloat16 smem[];
    float* sk_s = (float*)(smem + SK_OFF);
    float* sv_s = sk_s + 64;

    const uint32_t sb = smem_u32(smem);
    int tid = threadIdx.x;
    int wid = tid >> 5;
    int lane = tid & 31;
    int lrow = lane & 15;
    int lcol = (lane >> 4) << 3;   // 0 or 8
    int qr = lane >> 2;            // 0..7: fragment row within 8
    int qc = (lane & 3) << 1;      // 0,2,4,6: fragment col pair base

    int idx = blockIdx.x;
    int bh = idx & 63;
    int mt = 31 - (idx >> 6);      // heavy tiles first
    int b = bh >> 5, hq = bh & 31, hkv = hq >> 2;
    int m0 = mt * 64;

    // ---- load Q tile, split hi/lo bf16 ----
    {
        int c = tid & 31, r4 = tid >> 5;
        const float* qb = q + ((size_t)(b * SS + m0) * HQN + hq) * DD;
        #pragma unroll
        for (int j = 0; j < 16; ++j) {
            int m = j * 4 + r4;
            float4 v = *(const float4*)(qb + (size_t)m * HQN * DD + c * 4);
            float f[4] = {v.x * SCALING, v.y * SCALING, v.z * SCALING, v.w * SCALING};
            __nv_bfloat16 hh[4], ll[4];
            #pragma unroll
            for (int u = 0; u < 4; ++u) {
                hh[u] = __float2bfloat16_rn(f[u]);
                ll[u] = __float2bfloat16_rn(f[u] - __bfloat162float(hh[u]));
            }
            uint32_t* ph = (uint32_t*)(smem + OFF_QH + m * PITCH + c * 4);
            uint32_t* pl = (uint32_t*)(smem + OFF_QL + m * PITCH + c * 4);
            ph[0] = pack_bf16(hh[0], hh[1]); ph[1] = pack_bf16(hh[2], hh[3]);
            pl[0] = pack_bf16(ll[0], ll[1]); pl[1] = pack_bf16(ll[2], ll[3]);
        }
    }
    __syncthreads();

    const __nv_bfloat16* kgb = g_kg + (size_t)(b * HKV + hkv) * SS * DD;
    const __nv_bfloat16* vgb = g_vg + (size_t)(b * HKV + hkv) * SS * DD;
    const float* skg = g_sk + (size_t)(b * HKV + hkv) * SS;
    const float* svg = g_sv + (size_t)(b * HKV + hkv) * SS;

    // ldmatrix lane base addresses (bytes)
    const uint32_t qh_base = sb + (OFF_QH + (wid * 16 + lrow) * PITCH + lcol) * 2;
    const uint32_t ql_base = sb + (OFF_QL + (wid * 16 + lrow) * PITCH + lcol) * 2;
    const uint32_t k_base  = sb + (OFF_K + lrow * PITCH + lcol) * 2;
    const uint32_t v_base  = sb + (OFF_V + lrow * PITCH + lcol) * 2;

    float oacc[16][4];
    #pragma unroll
    for (int i = 0; i < 16; ++i)
        #pragma unroll
        for (int j = 0; j < 4; ++j) oacc[i][j] = 0.0f;
    float lsum0 = 0.0f, lsum1 = 0.0f;

    int rg0 = m0 + wid * 16 + qr;  // global row of c0,c1
    int rg1 = rg0 + 8;             // global row of c2,c3

    int ntiles = mt + 1;
    for (int t = 0; t < ntiles; ++t) {
        int n0 = t * 64;
        __syncthreads();  // previous iteration's smem readers done
        // ---- stage K/V tile + scales ----
        #pragma unroll
        for (int j = 0; j < 8; ++j) {
            int cidx = tid + j * 128;
            int row = cidx >> 4, ch = cidx & 15;
            uint4 kv = *(const uint4*)(kgb + (size_t)(n0 + row) * DD + ch * 8);
            *(uint4*)(smem + OFF_K + row * PITCH + ch * 8) = kv;
            uint4 vv = *(const uint4*)(vgb + (size_t)(n0 + row) * DD + ch * 8);
            *(uint4*)(smem + OFF_V + row * PITCH + ch * 8) = vv;
        }
        if (tid < 64) sk_s[tid] = skg[n0 + tid];
        else sv_s[tid - 64] = svg[n0 + tid - 64];
        __syncthreads();

        // ---- GEMM1: S(16x64 per warp) = (Qhi+Qlo) * K^T ----
        float sacc[8][4];
        #pragma unroll
        for (int i = 0; i < 8; ++i)
            #pragma unroll
            for (int j = 0; j < 4; ++j) sacc[i][j] = 0.0f;

        #pragma unroll
        for (int kc = 0; kc < 8; ++kc) {
            uint32_t qh[4], ql[4];
            LDSM4(qh, qh_base + kc * 32);
            LDSM4(ql, ql_base + kc * 32);
            #pragma unroll
            for (int nt2 = 0; nt2 < 4; ++nt2) {
                uint32_t kb[4];
                LDSM4(kb, k_base + nt2 * 16 * (PITCH * 2) + kc * 32);
                MMA_BF16(sacc[2 * nt2],     qh[0], qh[1], qh[2], qh[3], kb[0], kb[2]);
                MMA_BF16(sacc[2 * nt2 + 1], qh[0], qh[1], qh[2], qh[3], kb[1], kb[3]);
                MMA_BF16(sacc[2 * nt2],     ql[0], ql[1], ql[2], ql[3], kb[0], kb[2]);
                MMA_BF16(sacc[2 * nt2 + 1], ql[0], ql[1], ql[2], ql[3], kb[1], kb[3]);
            }
        }

        // ---- softmax + P hi/lo pack (register resident) ----
        bool diag = (t == ntiles - 1);
        uint32_t PH[8][2], PL[8][2];
        #pragma unroll
        for (int j = 0; j < 8; ++j) {
            int cg = n0 + j * 8 + qc;
            float s0 = sk_s[j * 8 + qc], s1 = sk_s[j * 8 + qc + 1];
            float v0 = sv_s[j * 8 + qc], v1 = sv_s[j * 8 + qc + 1];
            float e00 = __expf(sacc[j][0] * s0);
            float e01 = __expf(sacc[j][1] * s1);
            float e10 = __expf(sacc[j][2] * s0);
            float e11 = __expf(sacc[j][3] * s1);
            if (diag) {
                e00 = (cg     > rg0) ? 0.0f : e00;
                e01 = (cg + 1 > rg0) ? 0.0f : e01;
                e10 = (cg     > rg1) ? 0.0f : e10;
                e11 = (cg + 1 > rg1) ? 0.0f : e11;
            }
            lsum0 += e00 + e01;
            lsum1 += e10 + e11;
            float p00 = e00 * v0, p01 = e01 * v1;
            float p10 = e10 * v0, p11 = e11 * v1;
            __nv_bfloat16 h00 = __float2bfloat16_rn(p00), h01 = __float2bfloat16_rn(p01);
            __nv_bfloat16 h10 = __float2bfloat16_rn(p10), h11 = __float2bfloat16_rn(p11);
            __nv_bfloat16 l00 = __float2bfloat16_rn(p00 - __bfloat162float(h00));
            __nv_bfloat16 l01 = __float2bfloat16_rn(p01 - __bfloat162float(h01));
            __nv_bfloat16 l10 = __float2bfloat16_rn(p10 - __bfloat162float(h10));
            __nv_bfloat16 l11 = __float2bfloat16_rn(p11 - __bfloat162float(h11));
            PH[j][0] = pack_bf16(h00, h01); PH[j][1] = pack_bf16(h10, h11);
            PL[j][0] = pack_bf16(l00, l01); PL[j][1] = pack_bf16(l10, l11);
        }

        // ---- GEMM2: O(16x128 per warp) += (Phi+Plo) * V ----
        #pragma unroll
        for (int kt = 0; kt < 4; ++kt) {
            uint32_t ah0 = PH[2 * kt][0], ah1 = PH[2 * kt][1];
            uint32_t ah2 = PH[2 * kt + 1][0], ah3 = PH[2 * kt + 1][1];
            uint32_t al0 = PL[2 * kt][0], al1 = PL[2 * kt][1];
            uint32_t al2 = PL[2 * kt + 1][0], al3 = PL[2 * kt + 1][1];
            #pragma unroll
            for (int dt2 = 0; dt2 < 8; ++dt2) {
                uint32_t vb[4];
                LDSM4T(vb, v_base + kt * 16 * (PITCH * 2) + dt2 * 32);
                MMA_BF16(oacc[2 * dt2],     ah0, ah1, ah2, ah3, vb[0], vb[1]);
                MMA_BF16(oacc[2 * dt2 + 1], ah0, ah1, ah2, ah3, vb[2], vb[3]);
                MMA_BF16(oacc[2 * dt2],     al0, al1, al2, al3, vb[0], vb[1]);
                MMA_BF16(oacc[2 * dt2 + 1], al0, al1, al2, al3, vb[2], vb[3]);
            }
        }
    }

    // ---- epilogue ----
    lsum0 += __shfl_xor_sync(0xffffffffu, lsum0, 1);
    lsum0 += __shfl_xor_sync(0xffffffffu, lsum0, 2);
    lsum1 += __shfl_xor_sync(0xffffffffu, lsum1, 1);
    lsum1 += __shfl_xor_sync(0xffffffffu, lsum1, 2);
    float inv0 = 1.0f / lsum0, inv1 = 1.0f / lsum1;

    float* o0 = out + ((size_t)(b * SS + rg0) * HQN + hq) * DD;
    float* o1 = out + ((size_t)(b * SS + rg1) * HQN + hq) * DD;
    #pragma unroll
    for (int dt = 0; dt < 16; ++dt) {
        int d = dt * 8 + qc;
        *(float2*)(o0 + d) = make_float2(oacc[dt][0] * inv0, oacc[dt][1] * inv0);
        *(float2*)(o1 + d) = make_float2(oacc[dt][2] * inv1, oacc[dt][3] * inv1);
    }
}

extern "C" void kernel_launch(void* const* d_in, const int* in_sizes, int n_in,
                              void* d_out, int out_size) {
    (void)in_sizes; (void)n_in; (void)out_size;
    const float* q = (const float*)d_in[0];
    const float* k = (const float*)d_in[1];
    const float* v = (const float*)d_in[2];
    float* out = (float*)d_out;

    cudaFuncSetAttribute(attn_kernel, cudaFuncAttributeMaxDynamicSharedMemorySize,
                         SMEM_BYTES);

    int prep_rows = BB * SS * HKV;
    int prep_blocks = (prep_rows * 32 + 255) / 256;
    prep_kernel<<<prep_blocks, 256>>>(k, 0);
    prep_kernel<<<prep_blocks, 256>>>(v, 1);

    attn_kernel<<<(SS / 64) * BB * HQN, 128, SMEM_BYTES>>>(q, out);
}

// round 6
// speedup vs baseline: 8.0438x; 1.4885x over previous
#include <cuda_runtime.h>
#include <cuda_fp16.h>
#include <math.h>
#include <stdint.h>

#define BB 2
#define SS 2048
#define HQN 32
#define HKV 8
#define DD 128
#define SCALING 0.08838834764831845f

// ---------------- device scratch ----------------
__device__ __half g_kg[(size_t)BB * HKV * SS * DD];  // K fp4-grid f16 [b][h][s][d]
__device__ __half g_vg[(size_t)BB * HKV * SS * DD];  // V fp4-grid f16 [b][h][s][d]
__device__ float g_sk[(size_t)BB * HKV * SS];
__device__ float g_sv[(size_t)BB * HKV * SS];

// ---------------- prep: e4m3 qd (bit-exact) -> fp4 grid + scale ----------------
// Normal (|x| >= 2^-6): RNE to 3 mantissa bits via integer add (carry = next pow2),
// then clamp 448 (matches reference for all clip/round interactions).
// Subnormal (|x| < 2^-6): RNE at quantum 2^-9 via rintf(x*512)/512.
__device__ __forceinline__ float e4m3_qd(float x) {
    uint32_t u = __float_as_uint(x);
    uint32_t au = u & 0x7FFFFFFFu;
    float ax = __uint_as_float(au);
    uint32_t lsb = (au >> 20) & 1u;
    uint32_t r = au + 0x7FFFFu + lsb;
    float fn = fminf(__uint_as_float(r & 0xFFF00000u), 448.0f);
    float fs = rintf(ax * 512.0f) * (1.0f / 512.0f);
    float q = (ax < 0.015625f) ? fs : fn;
    return copysignf(q, x);
}

__global__ void prep_kernel(const float* __restrict__ ksrc, const float* __restrict__ vsrc) {
    int which = blockIdx.y;
    const float* __restrict__ src = which ? vsrc : ksrc;
    int gw = (blockIdx.x * blockDim.x + threadIdx.x) >> 5;
    if (gw >= BB * SS * HKV) return;
    int lane = threadIdx.x & 31;
    int h = gw % HKV;
    int t = gw / HKV;
    int s = t % SS;
    int b = t / SS;

    const float4* p = (const float4*)(src + ((size_t)(b * SS + s) * HKV + h) * DD);
    float4 xv = p[lane];
    float qq[4];
    qq[0] = e4m3_qd(xv.x); qq[1] = e4m3_qd(xv.y);
    qq[2] = e4m3_qd(xv.z); qq[3] = e4m3_qd(xv.w);

    float am = fmaxf(fmaxf(fabsf(qq[0]), fabsf(qq[1])), fmaxf(fabsf(qq[2]), fabsf(qq[3])));
    #pragma unroll
    for (int o = 16; o >= 1; o >>= 1)
        am = fmaxf(am, __shfl_xor_sync(0xffffffffu, am, o));
    float scale = fmaxf(__fdiv_rn(am, 6.0f), 1e-12f);

    float rr[4];
    #pragma unroll
    for (int u = 0; u < 4; ++u) {
        float xn = __fdiv_rn(qq[u], scale);
        float axn = fabsf(xn);
        float g = axn <= 0.25f ? 0.0f :
                  axn <= 0.75f ? 0.5f :
                  axn <= 1.25f ? 1.0f :
                  axn <= 1.75f ? 1.5f :
                  axn <= 2.5f  ? 2.0f :
                  axn <= 3.5f  ? 3.0f :
                  axn <= 5.0f  ? 4.0f : 6.0f;
        float sg = xn > 0.0f ? 1.0f : (xn < 0.0f ? -1.0f : 0.0f);
        rr[u] = sg * g;  // exact in fp16
    }

    size_t bh = (size_t)(b * HKV + h);
    __half* dst = (which ? g_vg : g_kg) + (bh * SS + s) * DD + lane * 4;
    dst[0] = __float2half_rn(rr[0]); dst[1] = __float2half_rn(rr[1]);
    dst[2] = __float2half_rn(rr[2]); dst[3] = __float2half_rn(rr[3]);
    if (lane == 0) (which ? g_sv : g_sk)[bh * SS + s] = scale;
}

// ---------------- mma.sync helpers ----------------
__device__ __forceinline__ uint32_t smem_u32(const void* p) {
    uint32_t a;
    asm("{ .reg .u64 t; cvta.to.shared.u64 t, %1; cvt.u32.u64 %0, t; }" : "=r"(a) : "l"(p));
    return a;
}

#define MMA_F16(c, a0, a1, a2, a3, b0, b1)                                      \
    asm volatile("mma.sync.aligned.m16n8k16.row.col.f32.f16.f16.f32 "           \
        "{%0,%1,%2,%3}, {%4,%5,%6,%7}, {%8,%9}, {%0,%1,%2,%3};"                 \
        : "+f"((c)[0]), "+f"((c)[1]), "+f"((c)[2]), "+f"((c)[3])                \
        : "r"(a0), "r"(a1), "r"(a2), "r"(a3), "r"(b0), "r"(b1))

#define LDSM4(r, a)                                                             \
    asm volatile("ldmatrix.sync.aligned.m8n8.x4.shared.b16 {%0,%1,%2,%3}, [%4];" \
        : "=r"((r)[0]), "=r"((r)[1]), "=r"((r)[2]), "=r"((r)[3]) : "r"(a))

#define LDSM4T(r, a)                                                            \
    asm volatile("ldmatrix.sync.aligned.m8n8.x4.trans.shared.b16 {%0,%1,%2,%3}, [%4];" \
        : "=r"((r)[0]), "=r"((r)[1]), "=r"((r)[2]), "=r"((r)[3]) : "r"(a))

#define CP16(dst, src) asm volatile("cp.async.cg.shared.global [%0], [%1], 16;" :: "r"(dst), "l"(src))
#define CP4(dst, src)  asm volatile("cp.async.ca.shared.global [%0], [%1], 4;" :: "r"(dst), "l"(src))
#define CPCOMMIT()     asm volatile("cp.async.commit_group;" ::: "memory")
#define CPWAIT1()      asm volatile("cp.async.wait_group 1;" ::: "memory")

__device__ __forceinline__ uint32_t pack_f16(float a, float b) {
    __half2 h = __floats2half2_rn(a, b);
    return *reinterpret_cast<uint32_t*>(&h);
}

// smem pitch: 136 halfs (272 B) per 128-elem row -> conflict-free ldmatrix
#define PITCH 136
#define OFF_Q  0
#define OFF_K0 (64 * PITCH)
#define OFF_K1 (2 * 64 * PITCH)
#define OFF_V0 (3 * 64 * PITCH)
#define OFF_V1 (4 * 64 * PITCH)
#define SC_OFF (5 * 64 * PITCH)              // 2 bufs x 128 floats
#define SMEM_HALFS (5 * 64 * PITCH + 512)
#define SMEM_BYTES (SMEM_HALFS * 2)

// ---------------- flash attention (fp16 mma, double-buffered) ----------------
__global__ __launch_bounds__(128)
void attn_kernel(const float* __restrict__ q, float* __restrict__ out) {
    extern __shared__ __align__(16) __half smem[];
    float* scf = (float*)(smem + SC_OFF);    // [buf][0..63]=sk, [64..127]=sv

    const uint32_t sb = smem_u32(smem);
    int tid = threadIdx.x;
    int wid = tid >> 5;
    int lane = tid & 31;
    int lrow = lane & 15;
    int lcol = (lane >> 4) << 3;
    int qr = lane >> 2;
    int qc = (lane & 3) << 1;

    int idx = blockIdx.x;
    int bh = idx & 63;
    int mt = 31 - (idx >> 6);      // heavy tiles first
    int b = bh >> 5, hq = bh & 31, hkv = hq >> 2;
    int m0 = mt * 64;

    const __half* kgb = g_kg + (size_t)(b * HKV + hkv) * SS * DD;
    const __half* vgb = g_vg + (size_t)(b * HKV + hkv) * SS * DD;
    const float* skg = g_sk + (size_t)(b * HKV + hkv) * SS;
    const float* svg = g_sv + (size_t)(b * HKV + hkv) * SS;

    int srow = tid >> 4, sch = tid & 15;     // staging: 8 rows per pass
    const uint32_t koff[2] = {sb + (OFF_K0 + srow * PITCH + sch * 8) * 2,
                              sb + (OFF_K1 + srow * PITCH + sch * 8) * 2};
    const uint32_t voff[2] = {sb + (OFF_V0 + srow * PITCH + sch * 8) * 2,
                              sb + (OFF_V1 + srow * PITCH + sch * 8) * 2};
    const uint32_t scoff = sb + SC_OFF * 2 + tid * 4;

    // ---- stage K/V tile t into buffer bf via cp.async ----
    auto stage = [&](int t, int bf) {
        int n0 = t * 64;
        const __half* kp = kgb + (size_t)(n0 + srow) * DD + sch * 8;
        const __half* vp = vgb + (size_t)(n0 + srow) * DD + sch * 8;
        #pragma unroll
        for (int j = 0; j < 8; ++j) {
            CP16(koff[bf] + j * 8 * PITCH * 2, kp + (size_t)j * 8 * DD);
            CP16(voff[bf] + j * 8 * PITCH * 2, vp + (size_t)j * 8 * DD);
        }
        const float* sp = (tid < 64) ? (skg + n0 + tid) : (svg + n0 + tid - 64);
        CP4(scoff + bf * 512, sp);
    };

    // ---- load Q tile to smem (fp16, single precision pass) ----
    {
        int c = tid & 31, r4 = tid >> 5;
        const float* qb = q + ((size_t)(b * SS + m0) * HQN + hq) * DD;
        #pragma unroll
        for (int j = 0; j < 16; ++j) {
            int m = j * 4 + r4;
            float4 v = *(const float4*)(qb + (size_t)m * HQN * DD + c * 4);
            uint32_t* ph = (uint32_t*)(smem + OFF_Q + m * PITCH + c * 4);
            ph[0] = pack_f16(v.x * SCALING, v.y * SCALING);
            ph[1] = pack_f16(v.z * SCALING, v.w * SCALING);
        }
    }
    stage(0, 0);
    CPCOMMIT();
    __syncthreads();

    // ---- hoist Q fragments (loop-invariant) ----
    const uint32_t q_base = sb + (OFF_Q + (wid * 16 + lrow) * PITCH + lcol) * 2;
    uint32_t qf[8][4];
    #pragma unroll
    for (int kc = 0; kc < 8; ++kc) LDSM4(qf[kc], q_base + kc * 32);

    const uint32_t k_base[2] = {sb + (OFF_K0 + lrow * PITCH + lcol) * 2,
                                sb + (OFF_K1 + lrow * PITCH + lcol) * 2};
    const uint32_t v_base[2] = {sb + (OFF_V0 + lrow * PITCH + lcol) * 2,
                                sb + (OFF_V1 + lrow * PITCH + lcol) * 2};

    float oacc[16][4];
    #pragma unroll
    for (int i = 0; i < 16; ++i)
        #pragma unroll
        for (int j = 0; j < 4; ++j) oacc[i][j] = 0.0f;
    float lsum0 = 0.0f, lsum1 = 0.0f;

    int rg0 = m0 + wid * 16 + qr;
    int rg1 = rg0 + 8;

    int ntiles = mt + 1;
    for (int t = 0; t < ntiles; ++t) {
        int bf = t & 1;
        if (t + 1 < ntiles) stage(t + 1, bf ^ 1);
        CPCOMMIT();
        CPWAIT1();
        __syncthreads();

        int n0 = t * 64;
        const float* sk_s = scf + bf * 128;
        const float* sv_s = sk_s + 64;

        // ---- GEMM1: S(16x64 per warp) = Q * K^T ----
        float sacc[8][4];
        #pragma unroll
        for (int i = 0; i < 8; ++i)
            #pragma unroll
            for (int j = 0; j < 4; ++j) sacc[i][j] = 0.0f;

        #pragma unroll
        for (int kc = 0; kc < 8; ++kc) {
            #pragma unroll
            for (int nt2 = 0; nt2 < 4; ++nt2) {
                uint32_t kb[4];
                LDSM4(kb, k_base[bf] + nt2 * 16 * (PITCH * 2) + kc * 32);
                MMA_F16(sacc[2 * nt2],     qf[kc][0], qf[kc][1], qf[kc][2], qf[kc][3], kb[0], kb[2]);
                MMA_F16(sacc[2 * nt2 + 1], qf[kc][0], qf[kc][1], qf[kc][2], qf[kc][3], kb[1], kb[3]);
            }
        }

        // ---- softmax + P pack (fp16, register resident) ----
        bool diag = (t == ntiles - 1);
        uint32_t P[8][2];
        #pragma unroll
        for (int j = 0; j < 8; ++j) {
            int cg = n0 + j * 8 + qc;
            float s0 = sk_s[j * 8 + qc], s1 = sk_s[j * 8 + qc + 1];
            float v0 = sv_s[j * 8 + qc], v1 = sv_s[j * 8 + qc + 1];
            float e00 = __expf(sacc[j][0] * s0);
            float e01 = __expf(sacc[j][1] * s1);
            float e10 = __expf(sacc[j][2] * s0);
            float e11 = __expf(sacc[j][3] * s1);
            if (diag) {
                e00 = (cg     > rg0) ? 0.0f : e00;
                e01 = (cg + 1 > rg0) ? 0.0f : e01;
                e10 = (cg     > rg1) ? 0.0f : e10;
                e11 = (cg + 1 > rg1) ? 0.0f : e11;
            }
            lsum0 += e00 + e01;
            lsum1 += e10 + e11;
            P[j][0] = pack_f16(e00 * v0, e01 * v1);
            P[j][1] = pack_f16(e10 * v0, e11 * v1);
        }

        // ---- GEMM2: O(16x128 per warp) += P * V ----
        #pragma unroll
        for (int kt = 0; kt < 4; ++kt) {
            uint32_t a0 = P[2 * kt][0], a1 = P[2 * kt][1];
            uint32_t a2 = P[2 * kt + 1][0], a3 = P[2 * kt + 1][1];
            #pragma unroll
            for (int dt2 = 0; dt2 < 8; ++dt2) {
                uint32_t vb[4];
                LDSM4T(vb, v_base[bf] + kt * 16 * (PITCH * 2) + dt2 * 32);
                MMA_F16(oacc[2 * dt2],     a0, a1, a2, a3, vb[0], vb[1]);
                MMA_F16(oacc[2 * dt2 + 1], a0, a1, a2, a3, vb[2], vb[3]);
            }
        }
        __syncthreads();  // readers done before buffer bf is re-staged at t+1
    }

    // ---- epilogue ----
    lsum0 += __shfl_xor_sync(0xffffffffu, lsum0, 1);
    lsum0 += __shfl_xor_sync(0xffffffffu, lsum0, 2);
    lsum1 += __shfl_xor_sync(0xffffffffu, lsum1, 1);
    lsum1 += __shfl_xor_sync(0xffffffffu, lsum1, 2);
    float inv0 = 1.0f / lsum0, inv1 = 1.0f / lsum1;

    float* o0 = out + ((size_t)(b * SS + rg0) * HQN + hq) * DD;
    float* o1 = out + ((size_t)(b * SS + rg1) * HQN + hq) * DD;
    #pragma unroll
    for (int dt = 0; dt < 16; ++dt) {
        int d = dt * 8 + qc;
        *(float2*)(o0 + d) = make_float2(oacc[dt][0] * inv0, oacc[dt][1] * inv0);
        *(float2*)(o1 + d) = make_float2(oacc[dt][2] * inv1, oacc[dt][3] * inv1);
    }
}

extern "C" void kernel_launch(void* const* d_in, const int* in_sizes, int n_in,
                              void* d_out, int out_size) {
    (void)in_sizes; (void)n_in; (void)out_size;
    const float* q = (const float*)d_in[0];
    const float* k = (const float*)d_in[1];
    const float* v = (const float*)d_in[2];
    float* out = (float*)d_out;

    cudaFuncSetAttribute(attn_kernel, cudaFuncAttributeMaxDynamicSharedMemorySize,
                         SMEM_BYTES);

    int prep_rows = BB * SS * HKV;
    dim3 pgrid((prep_rows * 32 + 255) / 256, 2);
    prep_kernel<<<pgrid, 256>>>(k, v);

    attn_kernel<<<(SS / 64) * BB * HQN, 128, SMEM_BYTES>>>(q, out);
}

// round 7
// speedup vs baseline: 8.4673x; 1.0526x over previous
#include <cuda_runtime.h>
#include <cuda_fp16.h>
#include <math.h>
#include <stdint.h>

#define BB 2
#define SS 2048
#define HQN 32
#define HKV 8
#define DD 128
#define SCALING 0.08838834764831845f

// ---------------- device scratch ----------------
__device__ __half g_kg[(size_t)BB * HKV * SS * DD];  // K fp4-grid f16 [b][h][s][d]
__device__ __half g_vg[(size_t)BB * HKV * SS * DD];  // V fp4-grid f16 [b][h][s][d]
__device__ float g_sk[(size_t)BB * HKV * SS];
__device__ float g_sv[(size_t)BB * HKV * SS];

// ---------------- prep: e4m3 qd (bit-exact) -> fp4 grid + scale ----------------
__device__ __forceinline__ float e4m3_qd(float x) {
    uint32_t u = __float_as_uint(x);
    uint32_t au = u & 0x7FFFFFFFu;
    float ax = __uint_as_float(au);
    uint32_t lsb = (au >> 20) & 1u;
    uint32_t r = au + 0x7FFFFu + lsb;
    float fn = fminf(__uint_as_float(r & 0xFFF00000u), 448.0f);
    float fs = rintf(ax * 512.0f) * (1.0f / 512.0f);
    float q = (ax < 0.015625f) ? fs : fn;
    return copysignf(q, x);
}

__global__ void prep_kernel(const float* __restrict__ ksrc, const float* __restrict__ vsrc) {
    int which = blockIdx.y;
    const float* __restrict__ src = which ? vsrc : ksrc;
    int gw = (blockIdx.x * blockDim.x + threadIdx.x) >> 5;
    if (gw >= BB * SS * HKV) return;
    int lane = threadIdx.x & 31;
    int h = gw % HKV;
    int t = gw / HKV;
    int s = t % SS;
    int b = t / SS;

    const float4* p = (const float4*)(src + ((size_t)(b * SS + s) * HKV + h) * DD);
    float4 xv = p[lane];
    float qq[4];
    qq[0] = e4m3_qd(xv.x); qq[1] = e4m3_qd(xv.y);
    qq[2] = e4m3_qd(xv.z); qq[3] = e4m3_qd(xv.w);

    float am = fmaxf(fmaxf(fabsf(qq[0]), fabsf(qq[1])), fmaxf(fabsf(qq[2]), fabsf(qq[3])));
    #pragma unroll
    for (int o = 16; o >= 1; o >>= 1)
        am = fmaxf(am, __shfl_xor_sync(0xffffffffu, am, o));
    float scale = fmaxf(__fdiv_rn(am, 6.0f), 1e-12f);

    float rr[4];
    #pragma unroll
    for (int u = 0; u < 4; ++u) {
        float xn = __fdiv_rn(qq[u], scale);
        float axn = fabsf(xn);
        float g = axn <= 0.25f ? 0.0f :
                  axn <= 0.75f ? 0.5f :
                  axn <= 1.25f ? 1.0f :
                  axn <= 1.75f ? 1.5f :
                  axn <= 2.5f  ? 2.0f :
                  axn <= 3.5f  ? 3.0f :
                  axn <= 5.0f  ? 4.0f : 6.0f;
        float sg = xn > 0.0f ? 1.0f : (xn < 0.0f ? -1.0f : 0.0f);
        rr[u] = sg * g;  // exact in fp16
    }

    size_t bh = (size_t)(b * HKV + h);
    __half* dst = (which ? g_vg : g_kg) + (bh * SS + s) * DD + lane * 4;
    dst[0] = __float2half_rn(rr[0]); dst[1] = __float2half_rn(rr[1]);
    dst[2] = __float2half_rn(rr[2]); dst[3] = __float2half_rn(rr[3]);
    if (lane == 0) (which ? g_sv : g_sk)[bh * SS + s] = scale;
}

// ---------------- mma.sync helpers ----------------
__device__ __forceinline__ uint32_t smem_u32(const void* p) {
    uint32_t a;
    asm("{ .reg .u64 t; cvta.to.shared.u64 t, %1; cvt.u32.u64 %0, t; }" : "=r"(a) : "l"(p));
    return a;
}

#define MMA_F16(c, a0, a1, a2, a3, b0, b1)                                      \
    asm volatile("mma.sync.aligned.m16n8k16.row.col.f32.f16.f16.f32 "           \
        "{%0,%1,%2,%3}, {%4,%5,%6,%7}, {%8,%9}, {%0,%1,%2,%3};"                 \
        : "+f"((c)[0]), "+f"((c)[1]), "+f"((c)[2]), "+f"((c)[3])                \
        : "r"(a0), "r"(a1), "r"(a2), "r"(a3), "r"(b0), "r"(b1))

#define LDSM4(r, a)                                                             \
    asm volatile("ldmatrix.sync.aligned.m8n8.x4.shared.b16 {%0,%1,%2,%3}, [%4];" \
        : "=r"((r)[0]), "=r"((r)[1]), "=r"((r)[2]), "=r"((r)[3]) : "r"(a))

#define LDSM4T(r, a)                                                            \
    asm volatile("ldmatrix.sync.aligned.m8n8.x4.trans.shared.b16 {%0,%1,%2,%3}, [%4];" \
        : "=r"((r)[0]), "=r"((r)[1]), "=r"((r)[2]), "=r"((r)[3]) : "r"(a))

#define CP16(dst, src) asm volatile("cp.async.cg.shared.global [%0], [%1], 16;" :: "r"(dst), "l"(src))
#define CP4(dst, src)  asm volatile("cp.async.ca.shared.global [%0], [%1], 4;" :: "r"(dst), "l"(src))
#define CPCOMMIT()     asm volatile("cp.async.commit_group;" ::: "memory")
#define CPWAIT1()      asm volatile("cp.async.wait_group 1;" ::: "memory")

__device__ __forceinline__ uint32_t pack_f16(float a, float b) {
    __half2 h = __floats2half2_rn(a, b);
    return *reinterpret_cast<uint32_t*>(&h);
}

// smem pitch: 136 halfs (272 B) per 128-elem row -> conflict-free ldmatrix.
// No dedicated Q region: Q is staged through the K0 buffer, hoisted to
// registers, then the pipeline overwrites it.
#define PITCH 136
#define OFF_K0 0
#define OFF_K1 (64 * PITCH)
#define OFF_V0 (2 * 64 * PITCH)
#define OFF_V1 (3 * 64 * PITCH)
#define SC_OFF (4 * 64 * PITCH)              // 2 bufs x 128 floats
#define SMEM_HALFS (4 * 64 * PITCH + 512)
#define SMEM_BYTES (SMEM_HALFS * 2)          // ~70 KB -> 3 CTAs/SM

// ---------------- flash attention (fp16 mma, double-buffered) ----------------
__global__ __launch_bounds__(128, 3)
void attn_kernel(const float* __restrict__ q, float* __restrict__ out) {
    extern __shared__ __align__(16) __half smem[];
    float* scf = (float*)(smem + SC_OFF);    // [buf][0..63]=sk, [64..127]=sv

    const uint32_t sb = smem_u32(smem);
    int tid = threadIdx.x;
    int wid = tid >> 5;
    int lane = tid & 31;
    int lrow = lane & 15;
    int lcol = (lane >> 4) << 3;
    int qr = lane >> 2;
    int qc = (lane & 3) << 1;

    int idx = blockIdx.x;
    int bh = idx & 63;
    int mt = 31 - (idx >> 6);      // heavy tiles first
    int b = bh >> 5, hq = bh & 31, hkv = hq >> 2;
    int m0 = mt * 64;

    const __half* kgb = g_kg + (size_t)(b * HKV + hkv) * SS * DD;
    const __half* vgb = g_vg + (size_t)(b * HKV + hkv) * SS * DD;
    const float* skg = g_sk + (size_t)(b * HKV + hkv) * SS;
    const float* svg = g_sv + (size_t)(b * HKV + hkv) * SS;

    int srow = tid >> 4, sch = tid & 15;     // staging: 8 rows per pass
    const uint32_t koff[2] = {sb + (OFF_K0 + srow * PITCH + sch * 8) * 2,
                              sb + (OFF_K1 + srow * PITCH + sch * 8) * 2};
    const uint32_t voff[2] = {sb + (OFF_V0 + srow * PITCH + sch * 8) * 2,
                              sb + (OFF_V1 + srow * PITCH + sch * 8) * 2};
    const uint32_t scoff = sb + SC_OFF * 2 + tid * 4;

    // ---- stage K/V tile t into buffer bf via cp.async ----
    auto stage = [&](int t, int bf) {
        int n0 = t * 64;
        const __half* kp = kgb + (size_t)(n0 + srow) * DD + sch * 8;
        const __half* vp = vgb + (size_t)(n0 + srow) * DD + sch * 8;
        #pragma unroll
        for (int j = 0; j < 8; ++j) {
            CP16(koff[bf] + j * 8 * PITCH * 2, kp + (size_t)j * 8 * DD);
            CP16(voff[bf] + j * 8 * PITCH * 2, vp + (size_t)j * 8 * DD);
        }
        const float* sp = (tid < 64) ? (skg + n0 + tid) : (svg + n0 + tid - 64);
        CP4(scoff + bf * 512, sp);
    };

    // ---- stage Q through the K0 region, hoist fragments, then free it ----
    {
        int c = tid & 31, r4 = tid >> 5;
        const float* qb = q + ((size_t)(b * SS + m0) * HQN + hq) * DD;
        #pragma unroll
        for (int j = 0; j < 16; ++j) {
            int m = j * 4 + r4;
            float4 v = *(const float4*)(qb + (size_t)m * HQN * DD + c * 4);
            uint32_t* ph = (uint32_t*)(smem + OFF_K0 + m * PITCH + c * 4);
            ph[0] = pack_f16(v.x * SCALING, v.y * SCALING);
            ph[1] = pack_f16(v.z * SCALING, v.w * SCALING);
        }
    }
    __syncthreads();
    uint32_t qf[8][4];
    {
        const uint32_t q_base = sb + (OFF_K0 + (wid * 16 + lrow) * PITCH + lcol) * 2;
        #pragma unroll
        for (int kc = 0; kc < 8; ++kc) LDSM4(qf[kc], q_base + kc * 32);
    }
    __syncthreads();  // all Q fragment reads done before K0 is overwritten

    stage(0, 0);
    CPCOMMIT();

    const uint32_t k_base[2] = {sb + (OFF_K0 + lrow * PITCH + lcol) * 2,
                                sb + (OFF_K1 + lrow * PITCH + lcol) * 2};
    const uint32_t v_base[2] = {sb + (OFF_V0 + lrow * PITCH + lcol) * 2,
                                sb + (OFF_V1 + lrow * PITCH + lcol) * 2};

    float oacc[16][4];
    #pragma unroll
    for (int i = 0; i < 16; ++i)
        #pragma unroll
        for (int j = 0; j < 4; ++j) oacc[i][j] = 0.0f;
    float lsum0 = 0.0f, lsum1 = 0.0f;

    int rg0 = m0 + wid * 16 + qr;
    int rg1 = rg0 + 8;

    int ntiles = mt + 1;
    for (int t = 0; t < ntiles; ++t) {
        int bf = t & 1;
        if (t + 1 < ntiles) stage(t + 1, bf ^ 1);
        CPCOMMIT();
        CPWAIT1();
        __syncthreads();

        int n0 = t * 64;
        const float* sk_s = scf + bf * 128;
        const float* sv_s = sk_s + 64;

        // ---- GEMM1: S(16x64 per warp) = Q * K^T ----
        float sacc[8][4];
        #pragma unroll
        for (int i = 0; i < 8; ++i)
            #pragma unroll
            for (int j = 0; j < 4; ++j) sacc[i][j] = 0.0f;

        #pragma unroll
        for (int kc = 0; kc < 8; ++kc) {
            #pragma unroll
            for (int nt2 = 0; nt2 < 4; ++nt2) {
                uint32_t kb[4];
                LDSM4(kb, k_base[bf] + nt2 * 16 * (PITCH * 2) + kc * 32);
                MMA_F16(sacc[2 * nt2],     qf[kc][0], qf[kc][1], qf[kc][2], qf[kc][3], kb[0], kb[2]);
                MMA_F16(sacc[2 * nt2 + 1], qf[kc][0], qf[kc][1], qf[kc][2], qf[kc][3], kb[1], kb[3]);
            }
        }

        // ---- softmax + P pack (fp16, register resident) ----
        bool diag = (t == ntiles - 1);
        uint32_t P[8][2];
        #pragma unroll
        for (int j = 0; j < 8; ++j) {
            int cg = n0 + j * 8 + qc;
            float2 sp = *(const float2*)(sk_s + j * 8 + qc);
            float2 vp = *(const float2*)(sv_s + j * 8 + qc);
            float e00 = __expf(sacc[j][0] * sp.x);
            float e01 = __expf(sacc[j][1] * sp.y);
            float e10 = __expf(sacc[j][2] * sp.x);
            float e11 = __expf(sacc[j][3] * sp.y);
            if (diag) {
                e00 = (cg     > rg0) ? 0.0f : e00;
                e01 = (cg + 1 > rg0) ? 0.0f : e01;
                e10 = (cg     > rg1) ? 0.0f : e10;
                e11 = (cg + 1 > rg1) ? 0.0f : e11;
            }
            lsum0 += e00 + e01;
            lsum1 += e10 + e11;
            P[j][0] = pack_f16(e00 * vp.x, e01 * vp.y);
            P[j][1] = pack_f16(e10 * vp.x, e11 * vp.y);
        }

        // ---- GEMM2: O(16x128 per warp) += P * V ----
        #pragma unroll
        for (int kt = 0; kt < 4; ++kt) {
            uint32_t a0 = P[2 * kt][0], a1 = P[2 * kt][1];
            uint32_t a2 = P[2 * kt + 1][0], a3 = P[2 * kt + 1][1];
            #pragma unroll
            for (int dt2 = 0; dt2 < 8; ++dt2) {
                uint32_t vb[4];
                LDSM4T(vb, v_base[bf] + kt * 16 * (PITCH * 2) + dt2 * 32);
                MMA_F16(oacc[2 * dt2],     a0, a1, a2, a3, vb[0], vb[1]);
                MMA_F16(oacc[2 * dt2 + 1], a0, a1, a2, a3, vb[2], vb[3]);
            }
        }
        __syncthreads();  // readers done before buffer bf is re-staged at t+1
    }

    // ---- epilogue ----
    lsum0 += __shfl_xor_sync(0xffffffffu, lsum0, 1);
    lsum0 += __shfl_xor_sync(0xffffffffu, lsum0, 2);
    lsum1 += __shfl_xor_sync(0xffffffffu, lsum1, 1);
    lsum1 += __shfl_xor_sync(0xffffffffu, lsum1, 2);
    float inv0 = 1.0f / lsum0, inv1 = 1.0f / lsum1;

    float* o0 = out + ((size_t)(b * SS + rg0) * HQN + hq) * DD;
    float* o1 = out + ((size_t)(b * SS + rg1) * HQN + hq) * DD;
    #pragma unroll
    for (int dt = 0; dt < 16; ++dt) {
        int d = dt * 8 + qc;
        *(float2*)(o0 + d) = make_float2(oacc[dt][0] * inv0, oacc[dt][1] * inv0);
        *(float2*)(o1 + d) = make_float2(oacc[dt][2] * inv1, oacc[dt][3] * inv1);
    }
}

extern "C" void kernel_launch(void* const* d_in, const int* in_sizes, int n_in,
                              void* d_out, int out_size) {
    (void)in_sizes; (void)n_in; (void)out_size;
    const float* q = (const float*)d_in[0];
    const float* k = (const float*)d_in[1];
    const float* v = (const float*)d_in[2];
    float* out = (float*)d_out;

    cudaFuncSetAttribute(attn_kernel, cudaFuncAttributeMaxDynamicSharedMemorySize,
                         SMEM_BYTES);

    int prep_rows = BB * SS * HKV;
    dim3 pgrid((prep_rows * 32 + 255) / 256, 2);
    prep_kernel<<<pgrid, 256>>>(k, v);

    attn_kernel<<<(SS / 64) * BB * HQN, 128, SMEM_BYTES>>>(q, out);
}

// round 8
// speedup vs baseline: 8.5802x; 1.0133x over previous
#include <cuda_runtime.h>
#include <cuda_fp16.h>
#include <math.h>
#include <stdint.h>

#define BB 2
#define SS 2048
#define HQN 32
#define HKV 8
#define DD 128
#define SCALING 0.08838834764831845f
#define LOG2E 1.4426950408889634f

// ---------------- device scratch ----------------
__device__ __half g_kg[(size_t)BB * HKV * SS * DD];  // K fp4-grid f16 [b][h][s][d]
__device__ __half g_vg[(size_t)BB * HKV * SS * DD];  // V fp4-grid f16 [b][h][s][d]
__device__ float g_sk[(size_t)BB * HKV * SS];        // sk * log2(e)  (prefolded)
__device__ float g_sv[(size_t)BB * HKV * SS];

// ---------------- prep: e4m3 qd (bit-exact) -> fp4 grid + scale ----------------
__device__ __forceinline__ float e4m3_qd(float x) {
    uint32_t u = __float_as_uint(x);
    uint32_t au = u & 0x7FFFFFFFu;
    float ax = __uint_as_float(au);
    uint32_t lsb = (au >> 20) & 1u;
    uint32_t r = au + 0x7FFFFu + lsb;
    float fn = fminf(__uint_as_float(r & 0xFFF00000u), 448.0f);
    float fs = rintf(ax * 512.0f) * (1.0f / 512.0f);
    float q = (ax < 0.015625f) ? fs : fn;
    return copysignf(q, x);
}

__global__ void prep_kernel(const float* __restrict__ ksrc, const float* __restrict__ vsrc) {
    int which = blockIdx.y;
    const float* __restrict__ src = which ? vsrc : ksrc;
    int gw = (blockIdx.x * blockDim.x + threadIdx.x) >> 5;
    if (gw >= BB * SS * HKV) return;
    int lane = threadIdx.x & 31;
    int h = gw % HKV;
    int t = gw / HKV;
    int s = t % SS;
    int b = t / SS;

    const float4* p = (const float4*)(src + ((size_t)(b * SS + s) * HKV + h) * DD);
    float4 xv = p[lane];
    float qq[4];
    qq[0] = e4m3_qd(xv.x); qq[1] = e4m3_qd(xv.y);
    qq[2] = e4m3_qd(xv.z); qq[3] = e4m3_qd(xv.w);

    float am = fmaxf(fmaxf(fabsf(qq[0]), fabsf(qq[1])), fmaxf(fabsf(qq[2]), fabsf(qq[3])));
    #pragma unroll
    for (int o = 16; o >= 1; o >>= 1)
        am = fmaxf(am, __shfl_xor_sync(0xffffffffu, am, o));
    float scale = fmaxf(__fdiv_rn(am, 6.0f), 1e-12f);

    float rr[4];
    #pragma unroll
    for (int u = 0; u < 4; ++u) {
        float xn = __fdiv_rn(qq[u], scale);
        float axn = fabsf(xn);
        float g = axn <= 0.25f ? 0.0f :
                  axn <= 0.75f ? 0.5f :
                  axn <= 1.25f ? 1.0f :
                  axn <= 1.75f ? 1.5f :
                  axn <= 2.5f  ? 2.0f :
                  axn <= 3.5f  ? 3.0f :
                  axn <= 5.0f  ? 4.0f : 6.0f;
        float sg = xn > 0.0f ? 1.0f : (xn < 0.0f ? -1.0f : 0.0f);
        rr[u] = sg * g;  // exact in fp16
    }

    size_t bh = (size_t)(b * HKV + h);
    __half* dst = (which ? g_vg : g_kg) + (bh * SS + s) * DD + lane * 4;
    dst[0] = __float2half_rn(rr[0]); dst[1] = __float2half_rn(rr[1]);
    dst[2] = __float2half_rn(rr[2]); dst[3] = __float2half_rn(rr[3]);
    if (lane == 0) {
        if (which) g_sv[bh * SS + s] = scale;
        else       g_sk[bh * SS + s] = scale * LOG2E;  // prefold for ex2
    }
}

// ---------------- mma.sync helpers ----------------
__device__ __forceinline__ uint32_t smem_u32(const void* p) {
    uint32_t a;
    asm("{ .reg .u64 t; cvta.to.shared.u64 t, %1; cvt.u32.u64 %0, t; }" : "=r"(a) : "l"(p));
    return a;
}
__device__ __forceinline__ float ex2f(float x) {
    float y;
    asm("ex2.approx.f32 %0, %1;" : "=f"(y) : "f"(x));
    return y;
}

#define MMA_F16(c, a0, a1, a2, a3, b0, b1)                                      \
    asm volatile("mma.sync.aligned.m16n8k16.row.col.f32.f16.f16.f32 "           \
        "{%0,%1,%2,%3}, {%4,%5,%6,%7}, {%8,%9}, {%0,%1,%2,%3};"                 \
        : "+f"((c)[0]), "+f"((c)[1]), "+f"((c)[2]), "+f"((c)[3])                \
        : "r"(a0), "r"(a1), "r"(a2), "r"(a3), "r"(b0), "r"(b1))

#define LDSM4(r, a)                                                             \
    asm volatile("ldmatrix.sync.aligned.m8n8.x4.shared.b16 {%0,%1,%2,%3}, [%4];" \
        : "=r"((r)[0]), "=r"((r)[1]), "=r"((r)[2]), "=r"((r)[3]) : "r"(a))

#define LDSM4T(r, a)                                                            \
    asm volatile("ldmatrix.sync.aligned.m8n8.x4.trans.shared.b16 {%0,%1,%2,%3}, [%4];" \
        : "=r"((r)[0]), "=r"((r)[1]), "=r"((r)[2]), "=r"((r)[3]) : "r"(a))

#define CP16(dst, src) asm volatile("cp.async.cg.shared.global [%0], [%1], 16;" :: "r"(dst), "l"(src))
#define CP4(dst, src)  asm volatile("cp.async.ca.shared.global [%0], [%1], 4;" :: "r"(dst), "l"(src))
#define CPCOMMIT()     asm volatile("cp.async.commit_group;" ::: "memory")
#define CPWAIT1()      asm volatile("cp.async.wait_group 1;" ::: "memory")

__device__ __forceinline__ uint32_t pack_f16(float a, float b) {
    __half2 h = __floats2half2_rn(a, b);
    return *reinterpret_cast<uint32_t*>(&h);
}

// smem pitch: 136 halfs (272 B) per 128-elem row -> conflict-free ldmatrix.
#define PITCH 136
#define OFF_K0 0
#define OFF_K1 (64 * PITCH)
#define OFF_V0 (2 * 64 * PITCH)
#define OFF_V1 (3 * 64 * PITCH)
#define SC_OFF (4 * 64 * PITCH)              // 2 bufs x 128 floats
#define SMEM_HALFS (4 * 64 * PITCH + 512)
#define SMEM_BYTES (SMEM_HALFS * 2)          // ~70 KB -> 3 CTAs/SM

// ---------------- flash attention (fp16 mma, double-buffered) ----------------
__global__ __launch_bounds__(128, 3)
void attn_kernel(const float* __restrict__ q, float* __restrict__ out) {
    extern __shared__ __align__(16) __half smem[];
    float* scf = (float*)(smem + SC_OFF);    // [buf][0..63]=sk*log2e, [64..127]=sv

    const uint32_t sb = smem_u32(smem);
    int tid = threadIdx.x;
    int wid = tid >> 5;
    int lane = tid & 31;
    int lrow = lane & 15;
    int lcol = (lane >> 4) << 3;
    int qr = lane >> 2;
    int qc = (lane & 3) << 1;

    int idx = blockIdx.x;
    int bh = idx & 63;
    int mt = 31 - (idx >> 6);      // heavy tiles first
    int b = bh >> 5, hq = bh & 31, hkv = hq >> 2;
    int m0 = mt * 64;

    const __half* kgb = g_kg + (size_t)(b * HKV + hkv) * SS * DD;
    const __half* vgb = g_vg + (size_t)(b * HKV + hkv) * SS * DD;
    const float* skg = g_sk + (size_t)(b * HKV + hkv) * SS;
    const float* svg = g_sv + (size_t)(b * HKV + hkv) * SS;

    int srow = tid >> 4, sch = tid & 15;     // staging: 8 rows per pass
    const uint32_t koff[2] = {sb + (OFF_K0 + srow * PITCH + sch * 8) * 2,
                              sb + (OFF_K1 + srow * PITCH + sch * 8) * 2};
    const uint32_t voff[2] = {sb + (OFF_V0 + srow * PITCH + sch * 8) * 2,
                              sb + (OFF_V1 + srow * PITCH + sch * 8) * 2};
    const uint32_t scoff = sb + SC_OFF * 2 + tid * 4;

    auto stage = [&](int t, int bf) {
        int n0 = t * 64;
        const __half* kp = kgb + (size_t)(n0 + srow) * DD + sch * 8;
        const __half* vp = vgb + (size_t)(n0 + srow) * DD + sch * 8;
        #pragma unroll
        for (int j = 0; j < 8; ++j) {
            CP16(koff[bf] + j * 8 * PITCH * 2, kp + (size_t)j * 8 * DD);
            CP16(voff[bf] + j * 8 * PITCH * 2, vp + (size_t)j * 8 * DD);
        }
        const float* sp = (tid < 64) ? (skg + n0 + tid) : (svg + n0 + tid - 64);
        CP4(scoff + bf * 512, sp);
    };

    // ---- stage Q through the K0 region, hoist fragments, then free it ----
    {
        int c = tid & 31, r4 = tid >> 5;
        const float* qb = q + ((size_t)(b * SS + m0) * HQN + hq) * DD;
        #pragma unroll
        for (int j = 0; j < 16; ++j) {
            int m = j * 4 + r4;
            float4 v = *(const float4*)(qb + (size_t)m * HQN * DD + c * 4);
            uint32_t* ph = (uint32_t*)(smem + OFF_K0 + m * PITCH + c * 4);
            ph[0] = pack_f16(v.x * SCALING, v.y * SCALING);
            ph[1] = pack_f16(v.z * SCALING, v.w * SCALING);
        }
    }
    __syncthreads();
    uint32_t qf[8][4];
    {
        const uint32_t q_base = sb + (OFF_K0 + (wid * 16 + lrow) * PITCH + lcol) * 2;
        #pragma unroll
        for (int kc = 0; kc < 8; ++kc) LDSM4(qf[kc], q_base + kc * 32);
    }
    __syncthreads();  // all Q fragment reads done before K0 is overwritten

    stage(0, 0);
    CPCOMMIT();

    const uint32_t k_base[2] = {sb + (OFF_K0 + lrow * PITCH + lcol) * 2,
                                sb + (OFF_K1 + lrow * PITCH + lcol) * 2};
    const uint32_t v_base[2] = {sb + (OFF_V0 + lrow * PITCH + lcol) * 2,
                                sb + (OFF_V1 + lrow * PITCH + lcol) * 2};

    float oacc[16][4];
    #pragma unroll
    for (int i = 0; i < 16; ++i)
        #pragma unroll
        for (int j = 0; j < 4; ++j) oacc[i][j] = 0.0f;
    float lsum0 = 0.0f, lsum1 = 0.0f;

    int rg0 = m0 + wid * 16 + qr;
    int rg1 = rg0 + 8;

    int ntiles = mt + 1;
    for (int t = 0; t < ntiles; ++t) {
        int bf = t & 1;
        if (t + 1 < ntiles) stage(t + 1, bf ^ 1);
        CPCOMMIT();
        CPWAIT1();
        __syncthreads();

        int n0 = t * 64;
        const float* sk_s = scf + bf * 128;
        const float* sv_s = sk_s + 64;

        // ---- GEMM1: S(16x64 per warp) = Q * K^T (grouped LDSM) ----
        float sacc[8][4];
        #pragma unroll
        for (int i = 0; i < 8; ++i)
            #pragma unroll
            for (int j = 0; j < 4; ++j) sacc[i][j] = 0.0f;

        #pragma unroll
        for (int kc = 0; kc < 8; ++kc) {
            #pragma unroll
            for (int g = 0; g < 2; ++g) {
                uint32_t kb0[4], kb1[4];
                LDSM4(kb0, k_base[bf] + (2 * g)     * 16 * (PITCH * 2) + kc * 32);
                LDSM4(kb1, k_base[bf] + (2 * g + 1) * 16 * (PITCH * 2) + kc * 32);
                MMA_F16(sacc[4 * g],     qf[kc][0], qf[kc][1], qf[kc][2], qf[kc][3], kb0[0], kb0[2]);
                MMA_F16(sacc[4 * g + 1], qf[kc][0], qf[kc][1], qf[kc][2], qf[kc][3], kb0[1], kb0[3]);
                MMA_F16(sacc[4 * g + 2], qf[kc][0], qf[kc][1], qf[kc][2], qf[kc][3], kb1[0], kb1[2]);
                MMA_F16(sacc[4 * g + 3], qf[kc][0], qf[kc][1], qf[kc][2], qf[kc][3], kb1[1], kb1[3]);
            }
        }

        // ---- softmax + P pack (ex2, register resident) ----
        bool diag = (t == ntiles - 1);
        uint32_t P[8][2];
        #pragma unroll
        for (int j = 0; j < 8; ++j) {
            int cg = n0 + j * 8 + qc;
            float2 sp = *(const float2*)(sk_s + j * 8 + qc);
            float2 vp = *(const float2*)(sv_s + j * 8 + qc);
            float t00 = sacc[j][0] * sp.x;
            float t01 = sacc[j][1] * sp.y;
            float t10 = sacc[j][2] * sp.x;
            float t11 = sacc[j][3] * sp.y;
            if (diag) {
                t00 = (cg     > rg0) ? -1e4f : t00;
                t01 = (cg + 1 > rg0) ? -1e4f : t01;
                t10 = (cg     > rg1) ? -1e4f : t10;
                t11 = (cg + 1 > rg1) ? -1e4f : t11;
            }
            float e00 = ex2f(t00), e01 = ex2f(t01);
            float e10 = ex2f(t10), e11 = ex2f(t11);
            lsum0 += e00 + e01;
            lsum1 += e10 + e11;
            P[j][0] = pack_f16(e00 * vp.x, e01 * vp.y);
            P[j][1] = pack_f16(e10 * vp.x, e11 * vp.y);
        }

        // ---- GEMM2: O(16x128 per warp) += P * V (grouped LDSM) ----
        #pragma unroll
        for (int kt = 0; kt < 4; ++kt) {
            uint32_t a0 = P[2 * kt][0], a1 = P[2 * kt][1];
            uint32_t a2 = P[2 * kt + 1][0], a3 = P[2 * kt + 1][1];
            #pragma unroll
            for (int g = 0; g < 4; ++g) {
                uint32_t vb0[4], vb1[4];
                LDSM4T(vb0, v_base[bf] + kt * 16 * (PITCH * 2) + (2 * g)     * 32);
                LDSM4T(vb1, v_base[bf] + kt * 16 * (PITCH * 2) + (2 * g + 1) * 32);
                MMA_F16(oacc[4 * g],     a0, a1, a2, a3, vb0[0], vb0[1]);
                MMA_F16(oacc[4 * g + 1], a0, a1, a2, a3, vb0[2], vb0[3]);
                MMA_F16(oacc[4 * g + 2], a0, a1, a2, a3, vb1[0], vb1[1]);
                MMA_F16(oacc[4 * g + 3], a0, a1, a2, a3, vb1[2], vb1[3]);
            }
        }
        __syncthreads();  // readers done before buffer bf is re-staged at t+1
    }

    // ---- epilogue ----
    lsum0 += __shfl_xor_sync(0xffffffffu, lsum0, 1);
    lsum0 += __shfl_xor_sync(0xffffffffu, lsum0, 2);
    lsum1 += __shfl_xor_sync(0xffffffffu, lsum1, 1);
    lsum1 += __shfl_xor_sync(0xffffffffu, lsum1, 2);
    float inv0 = 1.0f / lsum0, inv1 = 1.0f / lsum1;

    float* o0 = out + ((size_t)(b * SS + rg0) * HQN + hq) * DD;
    float* o1 = out + ((size_t)(b * SS + rg1) * HQN + hq) * DD;
    #pragma unroll
    for (int dt = 0; dt < 16; ++dt) {
        int d = dt * 8 + qc;
        *(float2*)(o0 + d) = make_float2(oacc[dt][0] * inv0, oacc[dt][1] * inv0);
        *(float2*)(o1 + d) = make_float2(oacc[dt][2] * inv1, oacc[dt][3] * inv1);
    }
}

extern "C" void kernel_launch(void* const* d_in, const int* in_sizes, int n_in,
                              void* d_out, int out_size) {
    (void)in_sizes; (void)n_in; (void)out_size;
    const float* q = (const float*)d_in[0];
    const float* k = (const float*)d_in[1];
    const float* v = (const float*)d_in[2];
    float* out = (float*)d_out;

    cudaFuncSetAttribute(attn_kernel, cudaFuncAttributeMaxDynamicSharedMemorySize,
                         SMEM_BYTES);

    int prep_rows = BB * SS * HKV;
    dim3 pgrid((prep_rows * 32 + 255) / 256, 2);
    prep_kernel<<<pgrid, 256>>>(k, v);

    attn_kernel<<<(SS / 64) * BB * HQN, 128, SMEM_BYTES>>>(q, out);
}